// round 1
// baseline (speedup 1.0000x reference)
#include <cuda_runtime.h>
#include <math_constants.h>

#define Bc 4
#define Nn 2048
#define DIMc 1024
#define HEADc 16
#define INTERc 1024
#define HDc 64
#define SCALEc 0.03125f   // INTER^-0.5

// Scratch (device globals: allocation-free per harness rules)
__device__ float g_qkv[(size_t)Bc * Nn * 3 * INTERc];  // [8192][3072]
__device__ float g_att[(size_t)Bc * Nn * INTERc];      // [8192][1024]

// ---------------------------------------------------------------------------
// SGEMM: C[M,Nc] = A[M,K] @ B[K,Nc], 128x128 tile, BK=8, 8x8 per thread
// ---------------------------------------------------------------------------
__global__ __launch_bounds__(256, 2)
void sgemm_kernel(const float* __restrict__ A, const float* __restrict__ B,
                  float* __restrict__ C, int M, int Nc, int K) {
    __shared__ float As[8][128];
    __shared__ float Bs[8][128];
    const int tid  = threadIdx.x;
    const int brow = blockIdx.y * 128;
    const int bcol = blockIdx.x * 128;
    const int a_row = tid >> 1;
    const int a_col = (tid & 1) << 2;
    const int b_row = tid >> 5;
    const int b_col = (tid & 31) << 2;
    const int ty = tid >> 4, tx = tid & 15;

    const float* Aptr = A + (size_t)(brow + a_row) * K + a_col;
    const float* Bptr = B + (size_t)b_row * Nc + bcol + b_col;

    float acc[8][8] = {};
    for (int k0 = 0; k0 < K; k0 += 8) {
        float4 av = *(const float4*)(Aptr + k0);
        float4 bv = *(const float4*)(Bptr + (size_t)k0 * Nc);
        As[a_col + 0][a_row] = av.x;
        As[a_col + 1][a_row] = av.y;
        As[a_col + 2][a_row] = av.z;
        As[a_col + 3][a_row] = av.w;
        *(float4*)&Bs[b_row][b_col] = bv;
        __syncthreads();
#pragma unroll
        for (int k = 0; k < 8; k++) {
            float4 a0 = *(const float4*)&As[k][ty * 8];
            float4 a1 = *(const float4*)&As[k][ty * 8 + 4];
            float4 b0 = *(const float4*)&Bs[k][tx * 8];
            float4 b1 = *(const float4*)&Bs[k][tx * 8 + 4];
            float ra[8] = {a0.x, a0.y, a0.z, a0.w, a1.x, a1.y, a1.z, a1.w};
            float rb[8] = {b0.x, b0.y, b0.z, b0.w, b1.x, b1.y, b1.z, b1.w};
#pragma unroll
            for (int m = 0; m < 8; m++)
#pragma unroll
                for (int n = 0; n < 8; n++)
                    acc[m][n] += ra[m] * rb[n];
        }
        __syncthreads();
    }
#pragma unroll
    for (int m = 0; m < 8; m++) {
        float* crow = C + (size_t)(brow + ty * 8 + m) * Nc + bcol + tx * 8;
        *(float4*)crow       = make_float4(acc[m][0], acc[m][1], acc[m][2], acc[m][3]);
        *(float4*)(crow + 4) = make_float4(acc[m][4], acc[m][5], acc[m][6], acc[m][7]);
    }
}

// ---------------------------------------------------------------------------
// Flash attention: one block per (b,h) x 64-row Q tile.
// 256 threads as 16x16; S and O tiles are 4x4 per thread (GEMM layout).
// Smem: Qs [d][i] (transposed), KP shared buffer (Ks [d][j] swizzled, then
// Ps [j][i^swz]), Vs [j][d]. Exactly 48KB static.
// ---------------------------------------------------------------------------
__global__ __launch_bounds__(256, 3)
void attn_kernel(const float* __restrict__ qkv, float* __restrict__ outp) {
    __shared__ float Qs[64 * 64];
    __shared__ float KP[64 * 64];   // K-tile, then aliased as P-tile
    __shared__ float Vs[64 * 64];

    const int tid = threadIdx.x;
    const int ty = tid >> 4, tx = tid & 15;
    const int bh = blockIdx.y;
    const int bI = bh >> 4;         // batch
    const int h  = bh & 15;         // head
    const int i0 = blockIdx.x << 6; // query row tile base

    const float* qb = qkv + ((size_t)bI * Nn) * (3 * INTERc) + h * HDc;
    const float* kb = qb + INTERc;
    const float* vb = qb + 2 * INTERc;

    // Load Q tile (pre-scaled), transposed [d][i]
#pragma unroll
    for (int r = 0; r < 4; r++) {
        int idx = tid + 256 * r;
        int i   = idx >> 4;
        int d0  = (idx & 15) << 2;
        float4 v = *(const float4*)(qb + (size_t)(i0 + i) * (3 * INTERc) + d0);
        Qs[(d0 + 0) * 64 + i] = v.x * SCALEc;
        Qs[(d0 + 1) * 64 + i] = v.y * SCALEc;
        Qs[(d0 + 2) * 64 + i] = v.z * SCALEc;
        Qs[(d0 + 3) * 64 + i] = v.w * SCALEc;
    }

    float acc[4][4] = {};
    float mrow[4], lrow[4];
#pragma unroll
    for (int m = 0; m < 4; m++) { mrow[m] = -CUDART_INF_F; lrow[m] = 0.f; }

    for (int jt = 0; jt < Nn; jt += 64) {
        __syncthreads();  // prev PV done reading Vs/KP; Qs visible on iter 0

        // Load K tile transposed+swizzled: element (d,j) ->
        // KP[d*64 + 4*((j>>2) ^ (d&15)) + (j&3)]  (4-way max STS conflicts)
        // Load V tile natural [j][d]
#pragma unroll
        for (int r = 0; r < 4; r++) {
            int idx = tid + 256 * r;
            int j   = idx >> 4;
            int d0  = (idx & 15) << 2;
            int jhi = j >> 2, jlo = j & 3;
            float4 kv = *(const float4*)(kb + (size_t)(jt + j) * (3 * INTERc) + d0);
            KP[(d0 + 0) * 64 + (((jhi ^ ((d0 + 0) & 15)) << 2) | jlo)] = kv.x;
            KP[(d0 + 1) * 64 + (((jhi ^ ((d0 + 1) & 15)) << 2) | jlo)] = kv.y;
            KP[(d0 + 2) * 64 + (((jhi ^ ((d0 + 2) & 15)) << 2) | jlo)] = kv.z;
            KP[(d0 + 3) * 64 + (((jhi ^ ((d0 + 3) & 15)) << 2) | jlo)] = kv.w;
            float4 vv = *(const float4*)(vb + (size_t)(jt + j) * (3 * INTERc) + d0);
            *(float4*)&Vs[j * 64 + d0] = vv;
        }
        __syncthreads();

        // S = (Q*SCALE) @ K^T : 4x4 per thread, i=4ty+m, j=4tx+n
        float s[4][4] = {};
#pragma unroll 16
        for (int d = 0; d < 64; d++) {
            float4 q  = *(const float4*)&Qs[d * 64 + ty * 4];
            float4 kk = *(const float4*)&KP[d * 64 + ((tx ^ (d & 15)) << 2)];
            float qv[4] = {q.x, q.y, q.z, q.w};
            float kvv[4] = {kk.x, kk.y, kk.z, kk.w};
#pragma unroll
            for (int m = 0; m < 4; m++)
#pragma unroll
                for (int n = 0; n < 4; n++)
                    s[m][n] += qv[m] * kvv[n];
        }

        // Online softmax: row reductions across the 16 lanes sharing ty
        float corr[4];
#pragma unroll
        for (int m = 0; m < 4; m++) {
            float v = fmaxf(fmaxf(s[m][0], s[m][1]), fmaxf(s[m][2], s[m][3]));
#pragma unroll
            for (int o = 8; o; o >>= 1)
                v = fmaxf(v, __shfl_xor_sync(0xffffffffu, v, o));
            float mn = fmaxf(mrow[m], v);
            corr[m]  = __expf(mrow[m] - mn);
            mrow[m]  = mn;
#pragma unroll
            for (int n = 0; n < 4; n++) s[m][n] = __expf(s[m][n] - mn);
            float ps = s[m][0] + s[m][1] + s[m][2] + s[m][3];
#pragma unroll
            for (int o = 8; o; o >>= 1)
                ps += __shfl_xor_sync(0xffffffffu, ps, o);
            lrow[m] = lrow[m] * corr[m] + ps;
#pragma unroll
            for (int n = 0; n < 4; n++) acc[m][n] *= corr[m];
        }
        __syncthreads();  // everyone done reading KP as K

        // Write P into KP: element (j,i) -> KP[j*64 + (i ^ (j>>2))]
#pragma unroll
        for (int n = 0; n < 4; n++) {
            int j = tx * 4 + n;
#pragma unroll
            for (int m = 0; m < 4; m++) {
                int i = ty * 4 + m;
                KP[j * 64 + (i ^ tx)] = s[m][n];
            }
        }
        __syncthreads();

        // O += P @ V : thread owns i=4ty+m, d=4tx+n
#pragma unroll 8
        for (int j = 0; j < 64; j++) {
            int sw = (j >> 2) & 15;
            float p0 = KP[j * 64 + ((ty * 4 + 0) ^ sw)];
            float p1 = KP[j * 64 + ((ty * 4 + 1) ^ sw)];
            float p2 = KP[j * 64 + ((ty * 4 + 2) ^ sw)];
            float p3 = KP[j * 64 + ((ty * 4 + 3) ^ sw)];
            float4 v = *(const float4*)&Vs[j * 64 + tx * 4];
            float vv[4] = {v.x, v.y, v.z, v.w};
            float pp[4] = {p0, p1, p2, p3};
#pragma unroll
            for (int m = 0; m < 4; m++)
#pragma unroll
                for (int n = 0; n < 4; n++)
                    acc[m][n] += pp[m] * vv[n];
        }
    }

    // Normalize and write O tile to g_att [b*N + i][h*64 + d]
#pragma unroll
    for (int m = 0; m < 4; m++) {
        float inv = 1.f / lrow[m];
        int row = i0 + ty * 4 + m;
        float4 o = make_float4(acc[m][0] * inv, acc[m][1] * inv,
                               acc[m][2] * inv, acc[m][3] * inv);
        *(float4*)(outp + (size_t)(bI * Nn + row) * INTERc + h * HDc + tx * 4) = o;
    }
}

// ---------------------------------------------------------------------------
extern "C" void kernel_launch(void* const* d_in, const int* in_sizes, int n_in,
                              void* d_out, int out_size) {
    const float* features = (const float*)d_in[0];
    const float* W_qkv    = (const float*)d_in[1];
    const float* W_out    = (const float*)d_in[2];
    float* out = (float*)d_out;

    float *qkv, *att;
    cudaGetSymbolAddress((void**)&qkv, g_qkv);
    cudaGetSymbolAddress((void**)&att, g_att);

    // 1) QKV projection: [8192,1024] @ [1024,3072]
    dim3 g1(3 * INTERc / 128, Bc * Nn / 128);
    sgemm_kernel<<<g1, 256>>>(features, W_qkv, qkv, Bc * Nn, 3 * INTERc, DIMc);

    // 2) Attention: 64 (b,h) pairs x 32 query tiles
    dim3 g2(Nn / 64, Bc * HEADc);
    attn_kernel<<<g2, 256>>>(qkv, att);

    // 3) Output projection: [8192,1024] @ [1024,1024]
    dim3 g3(DIMc / 128, Bc * Nn / 128);
    sgemm_kernel<<<g3, 256>>>(att, W_out, out, Bc * Nn, DIMc, INTERc);
}